// round 2
// baseline (speedup 1.0000x reference)
#include <cuda_runtime.h>
#include <cuda_bf16.h>
#include <math.h>

#define NMAX 100000
#define HID 128
#define PROTO 64
#define BN_EPS 1e-5f

// ---------------- scratch (device globals: no allocation allowed) ----------------
__device__ float g_h1[NMAX * HID];
__device__ float g_h2[NMAX * HID];
__device__ float g_agg[NMAX * HID];
__device__ float g_p[NMAX * HID];
__device__ float g_p2[NMAX * HID];
__device__ float g_an[NMAX * PROTO];
__device__ float g_sim[NMAX];
__device__ int   g_cnt[NMAX];
__device__ float g_sum[HID];
__device__ float g_sumsq[HID];
__device__ float g_scale[HID];
__device__ float g_shift[HID];

// ---------------- init ----------------
__global__ void init_kernel(int n) {
    int v = blockIdx.x * blockDim.x + threadIdx.x;
    if (v < n) { g_sim[v] = 1.0f; g_cnt[v] = 0; }  // self-loop sim == 1
}

__global__ void count_kernel(const int* __restrict__ tgt, int E) {
    int e = blockIdx.x * blockDim.x + threadIdx.x;
    if (e < E) atomicAdd(&g_cnt[tgt[e]], 1);
}

// ---------------- gate branch ----------------
__global__ void normalize_alpha_kernel(const float* __restrict__ alpha, int n) {
    int v = blockIdx.x * blockDim.x + threadIdx.x;
    if (v >= n) return;
    const float4* a = (const float4*)(alpha + (size_t)v * PROTO);
    float4 vals[16];
    float ss = 0.f;
#pragma unroll
    for (int i = 0; i < 16; i++) {
        vals[i] = a[i];
        ss += vals[i].x * vals[i].x + vals[i].y * vals[i].y +
              vals[i].z * vals[i].z + vals[i].w * vals[i].w;
    }
    float inv = 1.0f / fmaxf(sqrtf(ss), 1e-12f);
    float4* o = (float4*)(g_an + (size_t)v * PROTO);
#pragma unroll
    for (int i = 0; i < 16; i++) {
        float4 t = vals[i];
        t.x *= inv; t.y *= inv; t.z *= inv; t.w *= inv;
        o[i] = t;
    }
}

// 8 lanes per edge; cooperative dot over 64 floats
__global__ void edge_sim_kernel(const int* __restrict__ src, const int* __restrict__ tgt, int E) {
    long long gt = (long long)blockIdx.x * blockDim.x + threadIdx.x;
    long long eL = gt >> 3;
    bool valid = eL < (long long)E;
    int e = valid ? (int)eL : 0;
    int sub = ((int)gt & 7) * 8;
    int s = __ldg(src + e), t = __ldg(tgt + e);
    const float4* as = (const float4*)(g_an + (size_t)s * PROTO + sub);
    const float4* at = (const float4*)(g_an + (size_t)t * PROTO + sub);
    float4 a0 = as[0], a1 = as[1], b0 = at[0], b1 = at[1];
    float d = a0.x * b0.x + a0.y * b0.y + a0.z * b0.z + a0.w * b0.w +
              a1.x * b1.x + a1.y * b1.y + a1.z * b1.z + a1.w * b1.w;
    if (!valid) d = 0.f;
    d += __shfl_down_sync(0xFFFFFFFFu, d, 4);
    d += __shfl_down_sync(0xFFFFFFFFu, d, 2);
    d += __shfl_down_sync(0xFFFFFFFFu, d, 1);
    if (valid && ((gt & 7) == 0)) atomicAdd(&g_sim[t], d);
}

__global__ void gate_final_kernel(const float* __restrict__ temp, float* __restrict__ out, int n) {
    int v = blockIdx.x * blockDim.x + threadIdx.x;
    if (v >= n) return;
    float tv = __ldg(temp);
    float m = g_sim[v] / (float)(g_cnt[v] + 1);   // +1: self loop; always >= 1
    out[v] = 1.0f / (1.0f + expf(-tv * m));
}

// ---------------- scatter (segment sum) ----------------
// 32 threads per edge, one float4 each, vector RED into agg[tgt]
__global__ void scatter_kernel(const float* __restrict__ h, const int* __restrict__ src,
                               const int* __restrict__ tgt, int E) {
    long long gt = (long long)blockIdx.x * blockDim.x + threadIdx.x;
    long long eL = gt >> 5;
    if (eL >= (long long)E) return;
    int e = (int)eL;
    int c = ((int)gt & 31) * 4;
    int s = __ldg(src + e), t = __ldg(tgt + e);
    float4 v = *(const float4*)(h + (size_t)s * HID + c);
    float* dst = &g_agg[(size_t)t * HID + c];
    asm volatile("red.global.add.v4.f32 [%0], {%1,%2,%3,%4};"
                 :: "l"(dst), "f"(v.x), "f"(v.y), "f"(v.z), "f"(v.w) : "memory");
}

// ---------------- GEMM: C[r][c] = bias[c] + sum_k A1s[r][k]*W1[c][k] (+ A2[r][k]*W2[c][k]) ----------------
// tile: 64 rows x 128 cols, 256 threads, each thread 8 rows x 4 cols
template<int K, bool DUAL, bool MEAN1>
__global__ __launch_bounds__(256) void gemm_kernel(
    const float* __restrict__ A1, const float* __restrict__ A2,
    const float* __restrict__ W1, const float* __restrict__ W2,
    const float* __restrict__ bias, float* __restrict__ C, int n)
{
    constexpr int BM = 64, KC = 16;
    __shared__ float as1[BM][KC];
    __shared__ float as2[BM][KC];
    __shared__ float wt1[KC][HID];
    __shared__ float wt2[KC][HID];
    __shared__ float rinv[BM];

    const int tid  = threadIdx.x;
    const int lane = tid & 31;
    const int w    = tid >> 5;
    const int row0 = blockIdx.x * BM;

    if (MEAN1 && tid < BM) {
        int r = row0 + tid;
        int cv = (r < n) ? g_cnt[r] : 1;
        rinv[tid] = 1.0f / (float)(cv > 0 ? cv : 1);
    }

    float4 b4 = *(const float4*)(bias + lane * 4);
    float acc[8][4];
#pragma unroll
    for (int r = 0; r < 8; r++) { acc[r][0] = b4.x; acc[r][1] = b4.y; acc[r][2] = b4.z; acc[r][3] = b4.w; }

    for (int k0 = 0; k0 < K; k0 += KC) {
        __syncthreads();
        // A tiles (row-major in smem)
        for (int i = tid; i < BM * KC / 4; i += 256) {
            int r  = i / (KC / 4);
            int c4 = (i % (KC / 4)) * 4;
            int gr = row0 + r;
            float4 v = make_float4(0.f, 0.f, 0.f, 0.f);
            if (gr < n) v = *(const float4*)(A1 + (size_t)gr * K + k0 + c4);
            if (MEAN1) { float f = rinv[r]; v.x *= f; v.y *= f; v.z *= f; v.w *= f; }
            *(float4*)&as1[r][c4] = v;
            if (DUAL) {
                float4 u = make_float4(0.f, 0.f, 0.f, 0.f);
                if (gr < n) u = *(const float4*)(A2 + (size_t)gr * K + k0 + c4);
                *(float4*)&as2[r][c4] = u;
            }
        }
        // W tiles transposed: wt[k][c]
        {
            int c  = tid & 127;
            int kh = (tid >> 7) * (KC / 2);
#pragma unroll
            for (int j = 0; j < KC / 2; j += 4) {
                float4 v = *(const float4*)(W1 + (size_t)c * K + k0 + kh + j);
                wt1[kh + j + 0][c] = v.x; wt1[kh + j + 1][c] = v.y;
                wt1[kh + j + 2][c] = v.z; wt1[kh + j + 3][c] = v.w;
                if (DUAL) {
                    float4 u = *(const float4*)(W2 + (size_t)c * K + k0 + kh + j);
                    wt2[kh + j + 0][c] = u.x; wt2[kh + j + 1][c] = u.y;
                    wt2[kh + j + 2][c] = u.z; wt2[kh + j + 3][c] = u.w;
                }
            }
        }
        __syncthreads();
#pragma unroll
        for (int kk = 0; kk < KC; kk += 4) {
            float4 a1v[8], a2v[8];
#pragma unroll
            for (int r = 0; r < 8; r++) a1v[r] = *(float4*)&as1[w * 8 + r][kk];
            if (DUAL) {
#pragma unroll
                for (int r = 0; r < 8; r++) a2v[r] = *(float4*)&as2[w * 8 + r][kk];
            }
#pragma unroll
            for (int q = 0; q < 4; q++) {
                float4 wv = *(float4*)&wt1[kk + q][lane * 4];
#pragma unroll
                for (int r = 0; r < 8; r++) {
                    float a = (q == 0) ? a1v[r].x : (q == 1) ? a1v[r].y : (q == 2) ? a1v[r].z : a1v[r].w;
                    acc[r][0] += a * wv.x; acc[r][1] += a * wv.y;
                    acc[r][2] += a * wv.z; acc[r][3] += a * wv.w;
                }
                if (DUAL) {
                    float4 w2v = *(float4*)&wt2[kk + q][lane * 4];
#pragma unroll
                    for (int r = 0; r < 8; r++) {
                        float a = (q == 0) ? a2v[r].x : (q == 1) ? a2v[r].y : (q == 2) ? a2v[r].z : a2v[r].w;
                        acc[r][0] += a * w2v.x; acc[r][1] += a * w2v.y;
                        acc[r][2] += a * w2v.z; acc[r][3] += a * w2v.w;
                    }
                }
            }
        }
    }
#pragma unroll
    for (int r = 0; r < 8; r++) {
        int gr = row0 + w * 8 + r;
        if (gr < n) {
            float4 o = make_float4(acc[r][0], acc[r][1], acc[r][2], acc[r][3]);
            *(float4*)(C + (size_t)gr * HID + lane * 4) = o;
        }
    }
}

// ---------------- BN stats + apply ----------------
__global__ void zero_stats_kernel() {
    int c = threadIdx.x;
    g_sum[c] = 0.f; g_sumsq[c] = 0.f;
}

__global__ void colstats_kernel(const float* __restrict__ h, int n) {
    __shared__ float ssum[HID], ssq[HID];
    int tid = threadIdx.x, lane = tid & 31, w = tid >> 5;
    if (tid < HID) { ssum[tid] = 0.f; ssq[tid] = 0.f; }
    __syncthreads();
    int c = lane * 4;
    float4 s = make_float4(0, 0, 0, 0), q = make_float4(0, 0, 0, 0);
    int row0 = blockIdx.x * 512;
    int rend = min(row0 + 512, n);
    for (int r = row0 + w; r < rend; r += 8) {
        float4 v = *(const float4*)(h + (size_t)r * HID + c);
        s.x += v.x; s.y += v.y; s.z += v.z; s.w += v.w;
        q.x += v.x * v.x; q.y += v.y * v.y; q.z += v.z * v.z; q.w += v.w * v.w;
    }
    atomicAdd(&ssum[c + 0], s.x); atomicAdd(&ssum[c + 1], s.y);
    atomicAdd(&ssum[c + 2], s.z); atomicAdd(&ssum[c + 3], s.w);
    atomicAdd(&ssq[c + 0], q.x);  atomicAdd(&ssq[c + 1], q.y);
    atomicAdd(&ssq[c + 2], q.z);  atomicAdd(&ssq[c + 3], q.w);
    __syncthreads();
    if (tid < HID) {
        atomicAdd(&g_sum[tid], ssum[tid]);
        atomicAdd(&g_sumsq[tid], ssq[tid]);
    }
}

__global__ void stats_final_kernel(const float* __restrict__ gamma, const float* __restrict__ beta, float inv_n) {
    int c = threadIdx.x;
    float mu = g_sum[c] * inv_n;
    float var = g_sumsq[c] * inv_n - mu * mu;
    float sc = gamma[c] * rsqrtf(var + BN_EPS);
    g_scale[c] = sc;
    g_shift[c] = beta[c] - mu * sc;
}

// ACT: 0 = relu, 1 = sigmoid
template<int ACT>
__global__ void bn_act_kernel(float* __restrict__ h, int n) {
    size_t i = (size_t)blockIdx.x * blockDim.x + threadIdx.x;
    size_t total = (size_t)n * (HID / 4);
    if (i >= total) return;
    int c = (int)(i & 31) * 4;
    float4 v = ((float4*)h)[i];
    float4 sc = *(float4*)&g_scale[c];
    float4 sh = *(float4*)&g_shift[c];
    v.x = v.x * sc.x + sh.x; v.y = v.y * sc.y + sh.y;
    v.z = v.z * sc.z + sh.z; v.w = v.w * sc.w + sh.w;
    if (ACT == 0) {
        v.x = fmaxf(v.x, 0.f); v.y = fmaxf(v.y, 0.f);
        v.z = fmaxf(v.z, 0.f); v.w = fmaxf(v.w, 0.f);
    } else {
        v.x = 1.f / (1.f + expf(-v.x)); v.y = 1.f / (1.f + expf(-v.y));
        v.z = 1.f / (1.f + expf(-v.z)); v.w = 1.f / (1.f + expf(-v.w));
    }
    ((float4*)h)[i] = v;
}

// ---------------- classifier + log_softmax ----------------
__global__ __launch_bounds__(256) void classifier_kernel(
    const float* __restrict__ hg, const float* __restrict__ hp,
    const float* __restrict__ Wc, const float* __restrict__ bc,
    float* __restrict__ out, int n)
{
    __shared__ float wcs[40 * 256];
    __shared__ float bcs[40];
    int tid = threadIdx.x;
    for (int i = tid; i < 40 * 256; i += 256) wcs[i] = Wc[i];
    if (tid < 40) bcs[tid] = bc[tid];
    __syncthreads();
    int r = blockIdx.x * 256 + tid;
    if (r >= n) return;

    float acc[40];
#pragma unroll
    for (int o = 0; o < 40; o++) acc[o] = bcs[o];

    for (int half = 0; half < 2; half++) {
        const float* src = half ? hp : hg;
        for (int k4 = 0; k4 < 32; k4++) {
            float4 z = *(const float4*)(src + (size_t)r * HID + k4 * 4);
            z.x = fmaxf(z.x, 0.f); z.y = fmaxf(z.y, 0.f);
            z.z = fmaxf(z.z, 0.f); z.w = fmaxf(z.w, 0.f);
            int kb = half * 128 + k4 * 4;
#pragma unroll
            for (int o = 0; o < 40; o++) {
                float4 wv = *(float4*)&wcs[o * 256 + kb];
                acc[o] += z.x * wv.x + z.y * wv.y + z.z * wv.z + z.w * wv.w;
            }
        }
    }
    float m = acc[0];
#pragma unroll
    for (int o = 1; o < 40; o++) m = fmaxf(m, acc[o]);
    float s = 0.f;
#pragma unroll
    for (int o = 0; o < 40; o++) s += expf(acc[o] - m);
    float lse = m + logf(s);
    float* op = out + (size_t)r * 40;
#pragma unroll
    for (int o = 0; o < 40; o++) op[o] = acc[o] - lse;
}

// ---------------- launcher ----------------
extern "C" void kernel_launch(void* const* d_in, const int* in_sizes, int n_in,
                              void* d_out, int out_size) {
    const float* x           = (const float*)d_in[0];
    const float* alpha       = (const float*)d_in[1];
    const int*   ei          = (const int*)d_in[2];
    const float* sage_Wl     = (const float*)d_in[3];
    const float* sage_bl     = (const float*)d_in[4];
    const float* sage_Wr     = (const float*)d_in[5];
    const float* sage_bng    = (const float*)d_in[6];
    const float* sage_bnb    = (const float*)d_in[7];
    const float* mlp_W0      = (const float*)d_in[8];
    const float* mlp_b0      = (const float*)d_in[9];
    const float* mlp_W1      = (const float*)d_in[10];
    const float* mlp_b1      = (const float*)d_in[11];
    const float* mlp_W2      = (const float*)d_in[12];
    const float* mlp_b2      = (const float*)d_in[13];
    const float* mlp_bng     = (const float*)d_in[14];
    const float* mlp_bnb     = (const float*)d_in[15];
    const float* W_cls       = (const float*)d_in[16];
    const float* b_cls       = (const float*)d_in[17];
    const float* temperature = (const float*)d_in[18];

    int n = in_sizes[0] / HID;
    int E = in_sizes[2] / 2;
    const int* src = ei;
    const int* tgt = ei + E;
    float* out = (float*)d_out;

    float *h1, *h2, *agg, *p, *p2;
    cudaGetSymbolAddress((void**)&h1,  g_h1);
    cudaGetSymbolAddress((void**)&h2,  g_h2);
    cudaGetSymbolAddress((void**)&agg, g_agg);
    cudaGetSymbolAddress((void**)&p,   g_p);
    cudaGetSymbolAddress((void**)&p2,  g_p2);

    const int TB = 256;
    int nodeBlocks = (n + TB - 1) / TB;
    int gemmBlocks = (n + 63) / 64;
    float inv_n = 1.0f / (float)n;
    size_t aggBytes = (size_t)n * HID * sizeof(float);
    long long scatThreads = (long long)E * 32;
    int scatBlocks = (int)((scatThreads + TB - 1) / TB);
    long long simThreads = (long long)E * 8;
    int simBlocks = (int)((simThreads + TB - 1) / TB);
    int bnBlocks = (int)(((size_t)n * (HID / 4) + TB - 1) / TB);

    // ---- init + gate branch ----
    init_kernel<<<nodeBlocks, TB>>>(n);
    count_kernel<<<(E + TB - 1) / TB, TB>>>(tgt, E);
    normalize_alpha_kernel<<<nodeBlocks, TB>>>(alpha, n);
    edge_sim_kernel<<<simBlocks, TB>>>(src, tgt, E);
    gate_final_kernel<<<nodeBlocks, TB>>>(temperature, out + (size_t)n * 40, n);

    // ---- SAGE layer 0 ----
    cudaMemsetAsync(agg, 0, aggBytes);
    scatter_kernel<<<scatBlocks, TB>>>(x, src, tgt, E);
    gemm_kernel<128, true, true><<<gemmBlocks, TB>>>(agg, x, sage_Wl, sage_Wr, sage_bl, h1, n);
    zero_stats_kernel<<<1, HID>>>();
    colstats_kernel<<<(n + 511) / 512, TB>>>(h1, n);
    stats_final_kernel<<<1, HID>>>(sage_bng, sage_bnb, inv_n);
    bn_act_kernel<0><<<bnBlocks, TB>>>(h1, n);

    // ---- SAGE layer 1 ----
    cudaMemsetAsync(agg, 0, aggBytes);
    scatter_kernel<<<scatBlocks, TB>>>(h1, src, tgt, E);
    gemm_kernel<128, true, true><<<gemmBlocks, TB>>>(agg, h1, sage_Wl + 16384, sage_Wr + 16384,
                                                     sage_bl + HID, h2, n);
    zero_stats_kernel<<<1, HID>>>();
    colstats_kernel<<<(n + 511) / 512, TB>>>(h2, n);
    stats_final_kernel<<<1, HID>>>(sage_bng + HID, sage_bnb + HID, inv_n);
    bn_act_kernel<0><<<bnBlocks, TB>>>(h2, n);

    // ---- SAGE layer 2 (no BN/act) ----
    cudaMemsetAsync(agg, 0, aggBytes);
    scatter_kernel<<<scatBlocks, TB>>>(h2, src, tgt, E);
    gemm_kernel<128, true, true><<<gemmBlocks, TB>>>(agg, h2, sage_Wl + 32768, sage_Wr + 32768,
                                                     sage_bl + 2 * HID, h1, n);

    // ---- Proto MLP branch ----
    gemm_kernel<64, false, false><<<gemmBlocks, TB>>>(alpha, nullptr, mlp_W0, nullptr, mlp_b0, p, n);
    zero_stats_kernel<<<1, HID>>>();
    colstats_kernel<<<(n + 511) / 512, TB>>>(p, n);
    stats_final_kernel<<<1, HID>>>(mlp_bng, mlp_bnb, inv_n);
    bn_act_kernel<1><<<bnBlocks, TB>>>(p, n);

    gemm_kernel<128, false, false><<<gemmBlocks, TB>>>(p, nullptr, mlp_W1, nullptr, mlp_b1, p2, n);
    zero_stats_kernel<<<1, HID>>>();
    colstats_kernel<<<(n + 511) / 512, TB>>>(p2, n);
    stats_final_kernel<<<1, HID>>>(mlp_bng + HID, mlp_bnb + HID, inv_n);
    bn_act_kernel<1><<<bnBlocks, TB>>>(p2, n);

    gemm_kernel<128, false, false><<<gemmBlocks, TB>>>(p2, nullptr, mlp_W2, nullptr, mlp_b2, p, n);

    // ---- fusion + classifier + log_softmax ----
    classifier_kernel<<<nodeBlocks, TB>>>(h1, p, W_cls, b_cls, out, n);
}